// round 1
// baseline (speedup 1.0000x reference)
#include <cuda_runtime.h>
#include <math.h>

// Problem constants
#define B 512
#define V 6890
#define J 24
#define NB 10
#define P 207          // (J-1)*9
#define N3 (V*3)       // 20670

__constant__ int c_parents[J] = {0,0,0,0,1,2,3,4,5,6,7,8,9,9,9,12,13,14,16,17,18,19,20,21};

// Scratch (device globals; no runtime allocation allowed)
__device__ float g_jt[J*3];              // J_regressor @ v_template
__device__ float g_JS[J*3*NB];           // J_regressor @ shapedirs  [(j*3+k)*10+l]
__device__ float g_posefeat[B*P];        // (rot[1:]-I) flattened per batch
__device__ float g_rel[B*J*12];          // rel transforms, 3x4 row-major per joint
__device__ float g_vposed[(size_t)B*N3]; // v_shaped + pose correction

// ---------------------------------------------------------------------------
// K1: jt[j][k] = sum_v Jreg[j][v]*v_template[v][k]
//     JS[j][k][l] = sum_v Jreg[j][v]*shapedirs[v][k][l]
// grid (24, 33): y<3 -> jt component, else (y-3) = k*10+l
// ---------------------------------------------------------------------------
__global__ void k1_regress(const float* __restrict__ Jreg,
                           const float* __restrict__ vt,
                           const float* __restrict__ sd) {
    int j = blockIdx.x;
    int q = blockIdx.y;
    int tid = threadIdx.x;
    const float* jr = Jreg + (size_t)j * V;
    float acc = 0.f;
    if (q < 3) {
        for (int v = tid; v < V; v += 256) acc += jr[v] * vt[v*3 + q];
    } else {
        int kl = q - 3;
        for (int v = tid; v < V; v += 256) acc += jr[v] * sd[v*30 + kl];
    }
    __shared__ float red[256];
    red[tid] = acc;
    __syncthreads();
    for (int s = 128; s > 0; s >>= 1) {
        if (tid < s) red[tid] += red[tid + s];
        __syncthreads();
    }
    if (tid == 0) {
        if (q < 3) g_jt[j*3 + q] = red[0];
        else       g_JS[j*30 + (q-3)] = red[0];
    }
}

// ---------------------------------------------------------------------------
// K2: per-batch rodrigues, pose_feat, joints, kinematic chain, rel transforms.
// one warp per batch. Writes posed joints (+trans) into output tail.
// ---------------------------------------------------------------------------
__global__ void k2_pose(const float* __restrict__ ro,
                        const float* __restrict__ pb,
                        const float* __restrict__ ph,
                        const float* __restrict__ betas,
                        const float* __restrict__ trans,
                        float* __restrict__ out_joints) {
    int b = blockIdx.x;
    int lane = threadIdx.x;   // 32 threads

    __shared__ float rot[J][9];
    __shared__ float jnt[J][3];
    __shared__ float G[J][12];   // 3x4 affine, row-major

    if (lane < J) {
        float r0, r1, r2;
        if (lane == 0)        { const float* p = ro + b*3;                 r0=p[0]; r1=p[1]; r2=p[2]; }
        else if (lane <= 21)  { const float* p = pb + b*63 + (lane-1)*3;   r0=p[0]; r1=p[1]; r2=p[2]; }
        else                  { const float* p = ph + b*6  + (lane-22)*3;  r0=p[0]; r1=p[1]; r2=p[2]; }

        float a2  = r0*r0 + r1*r1 + r2*r2 + 1e-8f;
        float ang = sqrtf(a2);
        float inv = 1.f / ang;
        float x = r0*inv, y = r1*inv, z = r2*inv;
        float c = cosf(ang), s = sinf(ang), o = 1.f - c;

        float R[9];
        R[0] = c + o*x*x;     R[1] = -s*z + o*x*y;  R[2] =  s*y + o*x*z;
        R[3] =  s*z + o*y*x;  R[4] = c + o*y*y;     R[5] = -s*x + o*y*z;
        R[6] = -s*y + o*z*x;  R[7] =  s*x + o*z*y;  R[8] = c + o*z*z;

        #pragma unroll
        for (int e = 0; e < 9; e++) rot[lane][e] = R[e];

        if (lane >= 1) {
            float* pf = g_posefeat + (size_t)b*P + (lane-1)*9;
            #pragma unroll
            for (int e = 0; e < 9; e++)
                pf[e] = R[e] - ((e == 0 || e == 4 || e == 8) ? 1.f : 0.f);
        }

        // joints[j] = jt[j] + JS[j] . betas[b]
        float bt[NB];
        #pragma unroll
        for (int l = 0; l < NB; l++) bt[l] = betas[b*NB + l];
        #pragma unroll
        for (int k = 0; k < 3; k++) {
            float a = g_jt[lane*3 + k];
            #pragma unroll
            for (int l = 0; l < NB; l++) a += bt[l] * g_JS[lane*30 + k*10 + l];
            jnt[lane][k] = a;
        }
    }
    __syncthreads();

    if (lane == 0) {
        // root
        #pragma unroll
        for (int m = 0; m < 3; m++) {
            G[0][m*4+0] = rot[0][m*3+0];
            G[0][m*4+1] = rot[0][m*3+1];
            G[0][m*4+2] = rot[0][m*3+2];
            G[0][m*4+3] = jnt[0][m];
        }
        for (int j = 1; j < J; j++) {
            int p = c_parents[j];
            float t0 = jnt[j][0] - jnt[p][0];
            float t1 = jnt[j][1] - jnt[p][1];
            float t2 = jnt[j][2] - jnt[p][2];
            #pragma unroll
            for (int m = 0; m < 3; m++) {
                float p0 = G[p][m*4+0], p1 = G[p][m*4+1], p2 = G[p][m*4+2], p3 = G[p][m*4+3];
                G[j][m*4+0] = p0*rot[j][0] + p1*rot[j][3] + p2*rot[j][6];
                G[j][m*4+1] = p0*rot[j][1] + p1*rot[j][4] + p2*rot[j][7];
                G[j][m*4+2] = p0*rot[j][2] + p1*rot[j][5] + p2*rot[j][8];
                G[j][m*4+3] = p0*t0 + p1*t1 + p2*t2 + p3;
            }
        }
    }
    __syncthreads();

    if (lane < J) {
        int j = lane;
        float tx = trans[b*3+0], ty = trans[b*3+1], tz = trans[b*3+2];
        float* oj = out_joints + ((size_t)b*J + j)*3;
        oj[0] = G[j][3]  + tx;
        oj[1] = G[j][7]  + ty;
        oj[2] = G[j][11] + tz;

        float* rl = g_rel + ((size_t)b*J + j)*12;
        #pragma unroll
        for (int m = 0; m < 3; m++) {
            float corr = G[j][m*4+0]*jnt[j][0] + G[j][m*4+1]*jnt[j][1] + G[j][m*4+2]*jnt[j][2];
            rl[m*4+0] = G[j][m*4+0];
            rl[m*4+1] = G[j][m*4+1];
            rl[m*4+2] = G[j][m*4+2];
            rl[m*4+3] = G[j][m*4+3] - corr;
        }
    }
}

// ---------------------------------------------------------------------------
// K3: v_posed GEMM.  C[b, c] = sum_p pose_feat[b,p] * posedirs[p,c]
//                     + v_template[c] + sum_l betas[b,l]*shapedirs[c,l]
// 64x64 tile, BK=8, 256 threads, 4x4 microtile.
// ---------------------------------------------------------------------------
#define BM 64
#define BN 64
#define BK 8
__global__ void k3_gemm(const float* __restrict__ posedirs,
                        const float* __restrict__ vt,
                        const float* __restrict__ sd,
                        const float* __restrict__ betas) {
    __shared__ float As[BK][BM];
    __shared__ float Bs[BK][BN];

    int tid = threadIdx.x;
    int c0 = blockIdx.x * BN;
    int b0 = blockIdx.y * BM;
    int tx = tid & 15;
    int ty = tid >> 4;

    float acc[4][4];
    #pragma unroll
    for (int i = 0; i < 4; i++)
        #pragma unroll
        for (int k = 0; k < 4; k++) acc[i][k] = 0.f;

    for (int k0 = 0; k0 < P; k0 += BK) {
        // A tile: pose_feat[(b0+m), k0+p]
        {
            int m = tid >> 2;
            int pbase = tid & 3;
            #pragma unroll
            for (int pp = 0; pp < 2; pp++) {
                int p = pbase + pp*4;
                int kk = k0 + p;
                As[p][m] = (kk < P) ? g_posefeat[(size_t)(b0+m)*P + kk] : 0.f;
            }
        }
        // B tile: posedirs[k0+p, c0+c]
        {
            int p = tid >> 5;
            int cb = tid & 31;
            #pragma unroll
            for (int cc = 0; cc < 2; cc++) {
                int c = cb + cc*32;
                int kk = k0 + p;
                int col = c0 + c;
                Bs[p][c] = (kk < P && col < N3) ? posedirs[(size_t)kk*N3 + col] : 0.f;
            }
        }
        __syncthreads();

        #pragma unroll
        for (int p = 0; p < BK; p++) {
            float a[4], bb[4];
            #pragma unroll
            for (int i = 0; i < 4; i++) a[i]  = As[p][ty*4 + i];
            #pragma unroll
            for (int i = 0; i < 4; i++) bb[i] = Bs[p][tx*4 + i];
            #pragma unroll
            for (int iy = 0; iy < 4; iy++)
                #pragma unroll
                for (int ix = 0; ix < 4; ix++)
                    acc[iy][ix] += a[iy] * bb[ix];
        }
        __syncthreads();
    }

    // Epilogue: + v_template + betas . shapedirs, write g_vposed
    #pragma unroll
    for (int iy = 0; iy < 4; iy++) {
        int b = b0 + ty*4 + iy;
        float bt[NB];
        #pragma unroll
        for (int l = 0; l < NB; l++) bt[l] = betas[b*NB + l];
        #pragma unroll
        for (int ix = 0; ix < 4; ix++) {
            int c = c0 + tx*4 + ix;
            if (c < N3) {
                float val = acc[iy][ix] + vt[c];
                const float* sdc = sd + (size_t)c * NB;
                #pragma unroll
                for (int l = 0; l < NB; l++) val += bt[l] * sdc[l];
                g_vposed[(size_t)b*N3 + c] = val;
            }
        }
    }
}

// ---------------------------------------------------------------------------
// K4: skinning.  warp lanes = vertices (coalesced), 8 batches per block.
// T = sum_j w[v,j]*rel[b,j];  out = T * [vp,1] + trans
// ---------------------------------------------------------------------------
__global__ void k4_skin(const float* __restrict__ weights,
                        const float* __restrict__ trans,
                        float* __restrict__ out) {
    int tid = threadIdx.x;        // 256
    int warp = tid >> 5;
    int lane = tid & 31;
    int b = blockIdx.y * 8 + warp;

    __shared__ float s_rel[8][J*12];
    for (int i = tid; i < 8*J*12; i += 256) {
        int bl = i / (J*12), e = i % (J*12);
        s_rel[bl][e] = g_rel[((size_t)(blockIdx.y*8 + bl))*J*12 + e];
    }
    __syncthreads();

    float t0 = trans[b*3+0], t1 = trans[b*3+1], t2 = trans[b*3+2];
    const float* rel = s_rel[warp];
    const size_t bbase = (size_t)b * N3;

    for (int v = blockIdx.x*32 + lane; v < V; v += gridDim.x*32) {
        float T[12];
        #pragma unroll
        for (int m = 0; m < 12; m++) T[m] = 0.f;

        const float4* wv = reinterpret_cast<const float4*>(weights + (size_t)v * J);
        #pragma unroll
        for (int q = 0; q < 6; q++) {          // 6 x float4 = 24 weights
            float4 w4 = wv[q];
            const float* r0 = rel + (q*4 + 0)*12;
            const float* r1 = rel + (q*4 + 1)*12;
            const float* r2 = rel + (q*4 + 2)*12;
            const float* r3 = rel + (q*4 + 3)*12;
            #pragma unroll
            for (int m = 0; m < 12; m++)
                T[m] += w4.x*r0[m] + w4.y*r1[m] + w4.z*r2[m] + w4.w*r3[m];
        }

        float vx = g_vposed[bbase + v*3 + 0];
        float vy = g_vposed[bbase + v*3 + 1];
        float vz = g_vposed[bbase + v*3 + 2];

        float ox = T[0]*vx + T[1]*vy + T[2]*vz  + T[3]  + t0;
        float oy = T[4]*vx + T[5]*vy + T[6]*vz  + T[7]  + t1;
        float oz = T[8]*vx + T[9]*vy + T[10]*vz + T[11] + t2;

        float* o = out + ((size_t)b*V + v)*3;
        o[0] = ox; o[1] = oy; o[2] = oz;
    }
}

// ---------------------------------------------------------------------------
extern "C" void kernel_launch(void* const* d_in, const int* in_sizes, int n_in,
                              void* d_out, int out_size) {
    const float* root_orient = (const float*)d_in[0];
    const float* pose_body   = (const float*)d_in[1];
    const float* pose_hand   = (const float*)d_in[2];
    const float* betas       = (const float*)d_in[3];
    const float* trans       = (const float*)d_in[4];
    const float* v_template  = (const float*)d_in[5];
    const float* shapedirs   = (const float*)d_in[6];
    const float* posedirs    = (const float*)d_in[7];
    const float* J_regressor = (const float*)d_in[8];
    const float* weights     = (const float*)d_in[9];

    float* out = (float*)d_out;
    float* out_joints = out + (size_t)B * V * 3;

    k1_regress<<<dim3(J, 33), 256>>>(J_regressor, v_template, shapedirs);
    k2_pose<<<B, 32>>>(root_orient, pose_body, pose_hand, betas, trans, out_joints);
    k3_gemm<<<dim3((N3 + BN - 1)/BN, B/BM), 256>>>(posedirs, v_template, shapedirs, betas);
    k4_skin<<<dim3(54, B/8), 256>>>(weights, trans, out);
}

// round 3
// speedup vs baseline: 1.5720x; 1.5720x over previous
#include <cuda_runtime.h>
#include <math.h>

// Problem constants
#define B 512
#define V 6890
#define J 24
#define NB 10
#define P 207           // (J-1)*9
#define N3 (V*3)        // 20670
#define KA 218          // P + NB + 1 (posedirs rows + shapedirs rows + template row)
#define KPAD 224        // KA rounded up to BK multiple

__constant__ int c_parents[J] = {0,0,0,0,1,2,3,4,5,6,7,8,9,9,9,12,13,14,16,17,18,19,20,21};

// Scratch (device globals; no runtime allocation allowed)
__device__ float g_jt[J*3];               // J_regressor @ v_template
__device__ float g_JS[J*3*NB];            // J_regressor @ shapedirs
__device__ float g_AT[KPAD*B];            // A^T for the fused GEMM: [k][b]
__device__ float g_rel[B*J*12];           // rel transforms, 3x4 row-major per joint
__device__ float g_vposed[(size_t)B*N3];  // v_shaped + pose correction

// ---------------------------------------------------------------------------
// K1: jt[j][k] = sum_v Jreg[j][v]*v_template[v][k]
//     JS[j][k][l] = sum_v Jreg[j][v]*shapedirs[v][k][l]
// ---------------------------------------------------------------------------
__global__ void k1_regress(const float* __restrict__ Jreg,
                           const float* __restrict__ vt,
                           const float* __restrict__ sd) {
    int j = blockIdx.x;
    int q = blockIdx.y;
    int tid = threadIdx.x;
    const float* jr = Jreg + (size_t)j * V;
    float acc = 0.f;
    if (q < 3) {
        for (int v = tid; v < V; v += 256) acc += jr[v] * vt[v*3 + q];
    } else {
        int kl = q - 3;
        for (int v = tid; v < V; v += 256) acc += jr[v] * sd[v*30 + kl];
    }
    __shared__ float red[256];
    red[tid] = acc;
    __syncthreads();
    for (int s = 128; s > 0; s >>= 1) {
        if (tid < s) red[tid] += red[tid + s];
        __syncthreads();
    }
    if (tid == 0) {
        if (q < 3) g_jt[j*3 + q] = red[0];
        else       g_JS[j*30 + (q-3)] = red[0];
    }
}

// ---------------------------------------------------------------------------
// K2: per-batch rodrigues, kinematic chain, rel transforms. Also fills the
// transposed GEMM A-matrix g_AT (posefeat rows + betas rows + ones row + 0pad)
// so K3's A-loads are coalesced. One warp per batch.
// ---------------------------------------------------------------------------
__global__ void k2_pose(const float* __restrict__ ro,
                        const float* __restrict__ pb,
                        const float* __restrict__ ph,
                        const float* __restrict__ betas,
                        const float* __restrict__ trans,
                        float* __restrict__ out_joints) {
    int b = blockIdx.x;
    int lane = threadIdx.x;   // 32 threads

    __shared__ float rot[J][9];
    __shared__ float jnt[J][3];
    __shared__ float G[J][12];   // 3x4 affine, row-major

    if (lane < J) {
        float r0, r1, r2;
        if (lane == 0)        { const float* p = ro + b*3;                 r0=p[0]; r1=p[1]; r2=p[2]; }
        else if (lane <= 21)  { const float* p = pb + b*63 + (lane-1)*3;   r0=p[0]; r1=p[1]; r2=p[2]; }
        else                  { const float* p = ph + b*6  + (lane-22)*3;  r0=p[0]; r1=p[1]; r2=p[2]; }

        float a2  = r0*r0 + r1*r1 + r2*r2 + 1e-8f;
        float ang = sqrtf(a2);
        float inv = 1.f / ang;
        float x = r0*inv, y = r1*inv, z = r2*inv;
        float c = cosf(ang), s = sinf(ang), o = 1.f - c;

        float R[9];
        R[0] = c + o*x*x;     R[1] = -s*z + o*x*y;  R[2] =  s*y + o*x*z;
        R[3] =  s*z + o*y*x;  R[4] = c + o*y*y;     R[5] = -s*x + o*y*z;
        R[6] = -s*y + o*z*x;  R[7] =  s*x + o*z*y;  R[8] = c + o*z*z;

        #pragma unroll
        for (int e = 0; e < 9; e++) rot[lane][e] = R[e];

        if (lane >= 1) {
            int base = (lane-1)*9;
            #pragma unroll
            for (int e = 0; e < 9; e++)
                g_AT[(base+e)*B + b] = R[e] - ((e == 0 || e == 4 || e == 8) ? 1.f : 0.f);
        }

        // joints[j] = jt[j] + JS[j] . betas[b]
        float bt[NB];
        #pragma unroll
        for (int l = 0; l < NB; l++) bt[l] = betas[b*NB + l];
        #pragma unroll
        for (int k = 0; k < 3; k++) {
            float a = g_jt[lane*3 + k];
            #pragma unroll
            for (int l = 0; l < NB; l++) a += bt[l] * g_JS[lane*30 + k*10 + l];
            jnt[lane][k] = a;
        }
    }
    // Fill the extra GEMM A rows: betas (207..216), ones (217), zeros (218..223)
    if (lane < NB)                    g_AT[(P + lane)*B + b] = betas[b*NB + lane];
    if (lane == NB)                   g_AT[(P + NB)*B + b] = 1.f;
    if (lane >= 26)                   g_AT[(KA + lane - 26)*B + b] = 0.f;  // 6 pad rows
    __syncthreads();

    if (lane == 0) {
        #pragma unroll
        for (int m = 0; m < 3; m++) {
            G[0][m*4+0] = rot[0][m*3+0];
            G[0][m*4+1] = rot[0][m*3+1];
            G[0][m*4+2] = rot[0][m*3+2];
            G[0][m*4+3] = jnt[0][m];
        }
        for (int j = 1; j < J; j++) {
            int p = c_parents[j];
            float t0 = jnt[j][0] - jnt[p][0];
            float t1 = jnt[j][1] - jnt[p][1];
            float t2 = jnt[j][2] - jnt[p][2];
            #pragma unroll
            for (int m = 0; m < 3; m++) {
                float p0 = G[p][m*4+0], p1 = G[p][m*4+1], p2 = G[p][m*4+2], p3 = G[p][m*4+3];
                G[j][m*4+0] = p0*rot[j][0] + p1*rot[j][3] + p2*rot[j][6];
                G[j][m*4+1] = p0*rot[j][1] + p1*rot[j][4] + p2*rot[j][7];
                G[j][m*4+2] = p0*rot[j][2] + p1*rot[j][5] + p2*rot[j][8];
                G[j][m*4+3] = p0*t0 + p1*t1 + p2*t2 + p3;
            }
        }
    }
    __syncthreads();

    if (lane < J) {
        int j = lane;
        float tx = trans[b*3+0], ty = trans[b*3+1], tz = trans[b*3+2];
        float* oj = out_joints + ((size_t)b*J + j)*3;
        oj[0] = G[j][3]  + tx;
        oj[1] = G[j][7]  + ty;
        oj[2] = G[j][11] + tz;

        float* rl = g_rel + ((size_t)b*J + j)*12;
        #pragma unroll
        for (int m = 0; m < 3; m++) {
            float corr = G[j][m*4+0]*jnt[j][0] + G[j][m*4+1]*jnt[j][1] + G[j][m*4+2]*jnt[j][2];
            rl[m*4+0] = G[j][m*4+0];
            rl[m*4+1] = G[j][m*4+1];
            rl[m*4+2] = G[j][m*4+2];
            rl[m*4+3] = G[j][m*4+3] - corr;
        }
    }
}

// ---------------------------------------------------------------------------
// K3: fused GEMM.  vposed[b,c] = sum_{k<224} AT[k][b] * Brow(k)[c]
//   Brow(k) = posedirs[k]      (k < 207)
//           = shapedirs^T      (207 <= k < 217)
//           = v_template       (k == 217)
//           = 0                (k >= 218, AT also 0)
// Tile 64(B) x 128(cols) x 16, 256 threads, 4x8 microtile.
// ---------------------------------------------------------------------------
#define BM 64
#define BN 128
#define BK 16
__global__ void __launch_bounds__(256) k3_gemm(const float* __restrict__ posedirs,
                                               const float* __restrict__ vt,
                                               const float* __restrict__ sd) {
    __shared__ float As[BK][BM];
    __shared__ float Bs[BK][BN];

    int tid = threadIdx.x;
    int c0 = blockIdx.x * BN;
    int b0 = blockIdx.y * BM;
    int tx = tid & 15;       // 0..15 -> 8 cols each
    int ty = tid >> 4;       // 0..15 -> 4 rows each
    int ab = tid & 63;       // A load: batch index within tile
    int cc = (tid & 31) * 4; // B load: col base within tile

    float acc[4][8];
    #pragma unroll
    for (int i = 0; i < 4; i++)
        #pragma unroll
        for (int k = 0; k < 8; k++) acc[i][k] = 0.f;

    for (int k0 = 0; k0 < KPAD; k0 += BK) {
        // A tile: 64 x 16 = 1024, 4 coalesced scalars per thread
        #pragma unroll
        for (int i = 0; i < 4; i++) {
            int kk = (tid >> 6) + i*4;
            As[kk][ab] = g_AT[(k0 + kk)*B + b0 + ab];
        }
        // B tile: 16 x 128 = 2048, 8 per thread (two rows of 4)
        #pragma unroll
        for (int h = 0; h < 2; h++) {
            int kk = (tid >> 5) + h*8;
            int k = k0 + kk;
            #pragma unroll
            for (int e = 0; e < 4; e++) {
                int col = c0 + cc + e;
                float val = 0.f;
                if (col < N3) {
                    if (k < P)            val = posedirs[(size_t)k*N3 + col];
                    else if (k < P + NB)  val = sd[(size_t)col*NB + (k - P)];
                    else if (k == P + NB) val = vt[col];
                }
                Bs[kk][cc + e] = val;
            }
        }
        __syncthreads();

        #pragma unroll
        for (int p = 0; p < BK; p++) {
            float4 a   = *reinterpret_cast<const float4*>(&As[p][ty*4]);
            float4 bb0 = *reinterpret_cast<const float4*>(&Bs[p][tx*8]);
            float4 bb1 = *reinterpret_cast<const float4*>(&Bs[p][tx*8 + 4]);
            float av[4] = {a.x, a.y, a.z, a.w};
            float bv[8] = {bb0.x, bb0.y, bb0.z, bb0.w, bb1.x, bb1.y, bb1.z, bb1.w};
            #pragma unroll
            for (int iy = 0; iy < 4; iy++)
                #pragma unroll
                for (int ix = 0; ix < 8; ix++)
                    acc[iy][ix] += av[iy] * bv[ix];
        }
        __syncthreads();
    }

    // Store (float2, always 8B-aligned since N3, c0, tx*8 all even)
    #pragma unroll
    for (int iy = 0; iy < 4; iy++) {
        int b = b0 + ty*4 + iy;
        float* dst = g_vposed + (size_t)b*N3 + c0 + tx*8;
        #pragma unroll
        for (int ix = 0; ix < 8; ix += 2) {
            int col = c0 + tx*8 + ix;
            if (col + 1 < N3) {
                float2 v2 = make_float2(acc[iy][ix], acc[iy][ix+1]);
                *reinterpret_cast<float2*>(dst + ix) = v2;
            } else if (col < N3) {
                dst[ix] = acc[iy][ix];
            }
        }
    }
}

// ---------------------------------------------------------------------------
// K4: skinning, direct output accumulation (3 accumulators, not 12).
// out = trans + sum_j w[v,j] * (R_j*vp + t_j)   (identical algebra to T*[vp,1])
// One warp per batch slice, 4 vertices per lane; rel broadcast from smem.
// ---------------------------------------------------------------------------
__global__ void __launch_bounds__(256) k4_skin(const float* __restrict__ weights,
                                               const float* __restrict__ trans,
                                               float* __restrict__ out) {
    int tid = threadIdx.x;        // 256 = 8 warps
    int warp = tid >> 5;
    int lane = tid & 31;
    int b = blockIdx.y * 8 + warp;

    __shared__ float4 s_rel[8][J*3];   // 8 batches x 24 joints x 3 rows (float4)
    {
        const float4* src = reinterpret_cast<const float4*>(g_rel);
        for (int i = tid; i < 8*J*3; i += 256) {
            int bl = i / (J*3), e = i % (J*3);
            s_rel[bl][e] = src[(size_t)(blockIdx.y*8 + bl)*(J*3) + e];
        }
    }
    __syncthreads();

    float t0 = trans[b*3+0], t1 = trans[b*3+1], t2 = trans[b*3+2];
    const float4* rel = s_rel[warp];
    const size_t bbase = (size_t)b * N3;

    int v0 = blockIdx.x * 128;
    int v[4]; bool ok[4];
    float vx[4], vy[4], vz[4], ox[4], oy[4], oz[4];
    #pragma unroll
    for (int u = 0; u < 4; u++) {
        int vv = v0 + u*32 + lane;
        ok[u] = vv < V;
        v[u] = ok[u] ? vv : (V - 1);
        vx[u] = g_vposed[bbase + v[u]*3 + 0];
        vy[u] = g_vposed[bbase + v[u]*3 + 1];
        vz[u] = g_vposed[bbase + v[u]*3 + 2];
        ox[u] = t0; oy[u] = t1; oz[u] = t2;
    }

    const float4* wv0 = reinterpret_cast<const float4*>(weights + (size_t)v[0]*J);
    const float4* wv1 = reinterpret_cast<const float4*>(weights + (size_t)v[1]*J);
    const float4* wv2 = reinterpret_cast<const float4*>(weights + (size_t)v[2]*J);
    const float4* wv3 = reinterpret_cast<const float4*>(weights + (size_t)v[3]*J);

    #pragma unroll
    for (int q = 0; q < 6; q++) {
        float4 w[4];
        w[0] = wv0[q]; w[1] = wv1[q]; w[2] = wv2[q]; w[3] = wv3[q];
        #pragma unroll
        for (int jj = 0; jj < 4; jj++) {
            int j = q*4 + jj;
            float4 r0 = rel[j*3 + 0];
            float4 r1 = rel[j*3 + 1];
            float4 r2 = rel[j*3 + 2];
            #pragma unroll
            for (int u = 0; u < 4; u++) {
                float wj = (jj == 0) ? w[u].x : (jj == 1) ? w[u].y : (jj == 2) ? w[u].z : w[u].w;
                float rx = fmaf(r0.x, vx[u], fmaf(r0.y, vy[u], fmaf(r0.z, vz[u], r0.w)));
                float ry = fmaf(r1.x, vx[u], fmaf(r1.y, vy[u], fmaf(r1.z, vz[u], r1.w)));
                float rz = fmaf(r2.x, vx[u], fmaf(r2.y, vy[u], fmaf(r2.z, vz[u], r2.w)));
                ox[u] = fmaf(wj, rx, ox[u]);
                oy[u] = fmaf(wj, ry, oy[u]);
                oz[u] = fmaf(wj, rz, oz[u]);
            }
        }
    }

    #pragma unroll
    for (int u = 0; u < 4; u++) {
        if (ok[u]) {
            float* o = out + ((size_t)b*V + v[u])*3;
            o[0] = ox[u]; o[1] = oy[u]; o[2] = oz[u];
        }
    }
}

// ---------------------------------------------------------------------------
extern "C" void kernel_launch(void* const* d_in, const int* in_sizes, int n_in,
                              void* d_out, int out_size) {
    const float* root_orient = (const float*)d_in[0];
    const float* pose_body   = (const float*)d_in[1];
    const float* pose_hand   = (const float*)d_in[2];
    const float* betas       = (const float*)d_in[3];
    const float* trans       = (const float*)d_in[4];
    const float* v_template  = (const float*)d_in[5];
    const float* shapedirs   = (const float*)d_in[6];
    const float* posedirs    = (const float*)d_in[7];
    const float* J_regressor = (const float*)d_in[8];
    const float* weights     = (const float*)d_in[9];

    float* out = (float*)d_out;
    float* out_joints = out + (size_t)B * V * 3;

    k1_regress<<<dim3(J, 33), 256>>>(J_regressor, v_template, shapedirs);
    k2_pose<<<B, 32>>>(root_orient, pose_body, pose_hand, betas, trans, out_joints);
    k3_gemm<<<dim3((N3 + BN - 1)/BN, B/BM), 256>>>(posedirs, v_template, shapedirs);
    k4_skin<<<dim3((V + 127)/128, B/8), 256>>>(weights, trans, out);
}

// round 5
// speedup vs baseline: 3.0649x; 1.9497x over previous
#include <cuda_runtime.h>
#include <math.h>
#include <stdint.h>

// Problem constants
#define B 512
#define V 6890
#define J 24
#define NB 10
#define P 207           // (J-1)*9
#define N3 (V*3)        // 20670
#define KT 224          // padded GEMM K: 207 posedirs + 10 shapedirs + 7 zero
#define VS 20736        // padded column stride (162*128), multiple of 128

__constant__ int c_parents[J] = {0,0,0,0,1,2,3,4,5,6,7,8,9,9,9,12,13,14,16,17,18,19,20,21};

// Scratch (device globals; no runtime allocation allowed)
__device__ float g_jt[J*3];                 // J_regressor @ v_template
__device__ float g_JS[J*3*NB];              // J_regressor @ shapedirs
__device__ float g_AT[KT*B];                // A^T (tf32-rounded): [k][b]
__device__ float g_Bpack[(size_t)KT*VS];    // packed B (tf32-rounded): [k][c]
__device__ float g_rel[B*J*12];             // rel transforms, 3x4 row-major
__device__ float g_vposed[(size_t)B*VS];    // v_shaped + pose correction (padded)

// cvt.rna.tf32.f32 needs a .b32 destination register -> return bits as u32
__device__ __forceinline__ float tf32r(float x) {
    uint32_t y; asm("cvt.rna.tf32.f32 %0, %1;" : "=r"(y) : "f"(x));
    return __uint_as_float(y);
}

// f32x2 packed helpers
typedef unsigned long long u64;
__device__ __forceinline__ u64 pk2(float lo, float hi) {
    u64 r; asm("mov.b64 %0, {%1,%2};" : "=l"(r) : "f"(lo), "f"(hi)); return r;
}
__device__ __forceinline__ u64 fma2(u64 a, u64 b, u64 c) {
    u64 d; asm("fma.rn.f32x2 %0, %1, %2, %3;" : "=l"(d) : "l"(a), "l"(b), "l"(c)); return d;
}
__device__ __forceinline__ void upk(u64 v, float& lo, float& hi) {
    asm("mov.b64 {%0,%1}, %2;" : "=f"(lo), "=f"(hi) : "l"(v));
}

// ---------------------------------------------------------------------------
// K1: jt / JS regression (tiny)
// ---------------------------------------------------------------------------
__global__ void k1_regress(const float* __restrict__ Jreg,
                           const float* __restrict__ vt,
                           const float* __restrict__ sd) {
    int j = blockIdx.x;
    int q = blockIdx.y;
    int tid = threadIdx.x;
    const float* jr = Jreg + (size_t)j * V;
    float acc = 0.f;
    if (q < 3) {
        for (int v = tid; v < V; v += 256) acc += jr[v] * vt[v*3 + q];
    } else {
        int kl = q - 3;
        for (int v = tid; v < V; v += 256) acc += jr[v] * sd[v*30 + kl];
    }
    __shared__ float red[256];
    red[tid] = acc;
    __syncthreads();
    for (int s = 128; s > 0; s >>= 1) {
        if (tid < s) red[tid] += red[tid + s];
        __syncthreads();
    }
    if (tid == 0) {
        if (q < 3) g_jt[j*3 + q] = red[0];
        else       g_JS[j*30 + (q-3)] = red[0];
    }
}

// ---------------------------------------------------------------------------
// K0: pack B for the TF32 GEMM.  g_Bpack[k][c] (stride VS):
//   k < 207       : tf32(posedirs[k][c])
//   207 <= k < 217: tf32(shapedirs[c][k-207])   (transpose read)
//   k >= 217      : 0     (also c >= N3 -> 0)
// ---------------------------------------------------------------------------
__global__ void k0_pack(const float* __restrict__ posedirs,
                        const float* __restrict__ sd) {
    int k = blockIdx.y;
    int c = blockIdx.x * 256 + threadIdx.x;
    float val = 0.f;
    if (c < N3) {
        if (k < P)           val = tf32r(posedirs[(size_t)k*N3 + c]);
        else if (k < P + NB) val = tf32r(sd[(size_t)c*NB + (k - P)]);
    }
    g_Bpack[(size_t)k*VS + c] = val;
}

// ---------------------------------------------------------------------------
// K2: per-batch rodrigues, kinematic chain, rel transforms; fills g_AT
// (tf32-rounded posefeat rows + betas rows + zero pad). One warp per batch.
// ---------------------------------------------------------------------------
__global__ void k2_pose(const float* __restrict__ ro,
                        const float* __restrict__ pb,
                        const float* __restrict__ ph,
                        const float* __restrict__ betas,
                        const float* __restrict__ trans,
                        float* __restrict__ out_joints) {
    int b = blockIdx.x;
    int lane = threadIdx.x;   // 32 threads

    __shared__ float rot[J][9];
    __shared__ float jnt[J][3];
    __shared__ float G[J][12];

    if (lane < J) {
        float r0, r1, r2;
        if (lane == 0)        { const float* p = ro + b*3;                 r0=p[0]; r1=p[1]; r2=p[2]; }
        else if (lane <= 21)  { const float* p = pb + b*63 + (lane-1)*3;   r0=p[0]; r1=p[1]; r2=p[2]; }
        else                  { const float* p = ph + b*6  + (lane-22)*3;  r0=p[0]; r1=p[1]; r2=p[2]; }

        float a2  = r0*r0 + r1*r1 + r2*r2 + 1e-8f;
        float ang = sqrtf(a2);
        float inv = 1.f / ang;
        float x = r0*inv, y = r1*inv, z = r2*inv;
        float c = cosf(ang), s = sinf(ang), o = 1.f - c;

        float R[9];
        R[0] = c + o*x*x;     R[1] = -s*z + o*x*y;  R[2] =  s*y + o*x*z;
        R[3] =  s*z + o*y*x;  R[4] = c + o*y*y;     R[5] = -s*x + o*y*z;
        R[6] = -s*y + o*z*x;  R[7] =  s*x + o*z*y;  R[8] = c + o*z*z;

        #pragma unroll
        for (int e = 0; e < 9; e++) rot[lane][e] = R[e];

        if (lane >= 1) {
            int base = (lane-1)*9;
            #pragma unroll
            for (int e = 0; e < 9; e++)
                g_AT[(base+e)*B + b] = tf32r(R[e] - ((e == 0 || e == 4 || e == 8) ? 1.f : 0.f));
        }

        float bt[NB];
        #pragma unroll
        for (int l = 0; l < NB; l++) bt[l] = betas[b*NB + l];
        #pragma unroll
        for (int k = 0; k < 3; k++) {
            float a = g_jt[lane*3 + k];
            #pragma unroll
            for (int l = 0; l < NB; l++) a += bt[l] * g_JS[lane*30 + k*10 + l];
            jnt[lane][k] = a;
        }
    }
    // A rows: betas (207..216) tf32-rounded, zeros (217..223)
    if (lane < NB)  g_AT[(P + lane)*B + b] = tf32r(betas[b*NB + lane]);
    if (lane >= 25) g_AT[(192 + lane)*B + b] = 0.f;   // rows 217..223
    __syncthreads();

    if (lane == 0) {
        #pragma unroll
        for (int m = 0; m < 3; m++) {
            G[0][m*4+0] = rot[0][m*3+0];
            G[0][m*4+1] = rot[0][m*3+1];
            G[0][m*4+2] = rot[0][m*3+2];
            G[0][m*4+3] = jnt[0][m];
        }
        for (int j = 1; j < J; j++) {
            int p = c_parents[j];
            float t0 = jnt[j][0] - jnt[p][0];
            float t1 = jnt[j][1] - jnt[p][1];
            float t2 = jnt[j][2] - jnt[p][2];
            #pragma unroll
            for (int m = 0; m < 3; m++) {
                float p0 = G[p][m*4+0], p1 = G[p][m*4+1], p2 = G[p][m*4+2], p3 = G[p][m*4+3];
                G[j][m*4+0] = p0*rot[j][0] + p1*rot[j][3] + p2*rot[j][6];
                G[j][m*4+1] = p0*rot[j][1] + p1*rot[j][4] + p2*rot[j][7];
                G[j][m*4+2] = p0*rot[j][2] + p1*rot[j][5] + p2*rot[j][8];
                G[j][m*4+3] = p0*t0 + p1*t1 + p2*t2 + p3;
            }
        }
    }
    __syncthreads();

    if (lane < J) {
        int j = lane;
        float tx = trans[b*3+0], ty = trans[b*3+1], tz = trans[b*3+2];
        float* oj = out_joints + ((size_t)b*J + j)*3;
        oj[0] = G[j][3]  + tx;
        oj[1] = G[j][7]  + ty;
        oj[2] = G[j][11] + tz;

        float* rl = g_rel + ((size_t)b*J + j)*12;
        #pragma unroll
        for (int m = 0; m < 3; m++) {
            float corr = G[j][m*4+0]*jnt[j][0] + G[j][m*4+1]*jnt[j][1] + G[j][m*4+2]*jnt[j][2];
            rl[m*4+0] = G[j][m*4+0];
            rl[m*4+1] = G[j][m*4+1];
            rl[m*4+2] = G[j][m*4+2];
            rl[m*4+3] = G[j][m*4+3] - corr;
        }
    }
}

// ---------------------------------------------------------------------------
// K3: TF32 tensor-core GEMM.  vposed[b][c] = sum_k AT[k][b]*Bpack[k][c] + vt[c]
// Block: 128(batch) x 128(cols), 8 warps (2x4), warp tile 64x32,
// m16n8k8 mma, BK=16 double-buffered smem, stride 136 (conflict-free).
// ---------------------------------------------------------------------------
#define BK3 16
#define SST 136
__global__ void __launch_bounds__(256) k3_tf32(const float* __restrict__ vt) {
    __shared__ float sA[2][BK3][SST];
    __shared__ float sB[2][BK3][SST];

    int tid  = threadIdx.x;
    int warp = tid >> 5, lane = tid & 31;
    int wm = warp >> 2;          // 0..1 (batch dir)
    int wn = warp & 3;           // 0..3 (col dir)
    int gr = lane >> 2;          // 0..7
    int tg = lane & 3;           // 0..3

    int c0 = blockIdx.x * 128;
    int b0 = blockIdx.y * 128;

    // loaders
    int lk = tid >> 4;           // 0..15
    int lc = (tid & 15) * 8;     // 0..120

    float acc[4][4][4];
    #pragma unroll
    for (int mi = 0; mi < 4; mi++)
        #pragma unroll
        for (int ni = 0; ni < 4; ni++)
            #pragma unroll
            for (int r = 0; r < 4; r++) acc[mi][ni][r] = 0.f;

    // preload stage 0
    {
        const float4* ga = reinterpret_cast<const float4*>(g_AT + (size_t)lk*B + b0 + lc);
        const float4* gb = reinterpret_cast<const float4*>(g_Bpack + (size_t)lk*VS + c0 + lc);
        float4 a0 = ga[0], a1 = ga[1];
        float4 bq0 = gb[0], bq1 = gb[1];
        *reinterpret_cast<float4*>(&sA[0][lk][lc])     = a0;
        *reinterpret_cast<float4*>(&sA[0][lk][lc + 4]) = a1;
        *reinterpret_cast<float4*>(&sB[0][lk][lc])     = bq0;
        *reinterpret_cast<float4*>(&sB[0][lk][lc + 4]) = bq1;
    }
    __syncthreads();

    const int NST = KT / BK3;    // 14
    for (int st = 0; st < NST; st++) {
        float4 pa0, pa1, pb0, pb1;
        bool has_next = (st + 1 < NST);
        if (has_next) {
            int k = (st + 1) * BK3 + lk;
            const float4* ga = reinterpret_cast<const float4*>(g_AT + (size_t)k*B + b0 + lc);
            const float4* gb = reinterpret_cast<const float4*>(g_Bpack + (size_t)k*VS + c0 + lc);
            pa0 = ga[0]; pa1 = ga[1];
            pb0 = gb[0]; pb1 = gb[1];
        }
        int buf = st & 1;

        #pragma unroll
        for (int ks = 0; ks < 2; ks++) {
            int kb = ks * 8;
            uint32_t bfr[4][2];
            #pragma unroll
            for (int ni = 0; ni < 4; ni++) {
                int n = wn*32 + ni*8 + gr;
                bfr[ni][0] = __float_as_uint(sB[buf][kb + tg][n]);
                bfr[ni][1] = __float_as_uint(sB[buf][kb + tg + 4][n]);
            }
            uint32_t afr[4][4];
            #pragma unroll
            for (int mi = 0; mi < 4; mi++) {
                int m = wm*64 + mi*16 + gr;
                afr[mi][0] = __float_as_uint(sA[buf][kb + tg][m]);
                afr[mi][1] = __float_as_uint(sA[buf][kb + tg][m + 8]);
                afr[mi][2] = __float_as_uint(sA[buf][kb + tg + 4][m]);
                afr[mi][3] = __float_as_uint(sA[buf][kb + tg + 4][m + 8]);
            }
            #pragma unroll
            for (int mi = 0; mi < 4; mi++)
                #pragma unroll
                for (int ni = 0; ni < 4; ni++) {
                    asm volatile(
                        "mma.sync.aligned.m16n8k8.row.col.f32.tf32.tf32.f32 "
                        "{%0,%1,%2,%3}, {%4,%5,%6,%7}, {%8,%9}, {%0,%1,%2,%3};\n"
                        : "+f"(acc[mi][ni][0]), "+f"(acc[mi][ni][1]),
                          "+f"(acc[mi][ni][2]), "+f"(acc[mi][ni][3])
                        : "r"(afr[mi][0]), "r"(afr[mi][1]), "r"(afr[mi][2]), "r"(afr[mi][3]),
                          "r"(bfr[ni][0]), "r"(bfr[ni][1]));
                }
        }

        if (has_next) {
            int nb = 1 - buf;
            *reinterpret_cast<float4*>(&sA[nb][lk][lc])     = pa0;
            *reinterpret_cast<float4*>(&sA[nb][lk][lc + 4]) = pa1;
            *reinterpret_cast<float4*>(&sB[nb][lk][lc])     = pb0;
            *reinterpret_cast<float4*>(&sB[nb][lk][lc + 4]) = pb1;
            __syncthreads();
        }
    }

    // Epilogue: + v_template (fp32), store padded vposed (float2)
    #pragma unroll
    for (int mi = 0; mi < 4; mi++) {
        #pragma unroll
        for (int half = 0; half < 2; half++) {
            int b = b0 + wm*64 + mi*16 + gr + half*8;
            #pragma unroll
            for (int ni = 0; ni < 4; ni++) {
                int c = c0 + wn*32 + ni*8 + tg*2;
                float v0 = (c     < N3) ? vt[c]     : 0.f;
                float v1 = (c + 1 < N3) ? vt[c + 1] : 0.f;
                float2 o = make_float2(acc[mi][ni][half*2]     + v0,
                                       acc[mi][ni][half*2 + 1] + v1);
                *reinterpret_cast<float2*>(g_vposed + (size_t)b*VS + c) = o;
            }
        }
    }
}

// ---------------------------------------------------------------------------
// K4: skinning with packed f32x2 FMA. 4 verts/lane as 2 packed pairs.
// out = trans + sum_j w[v,j] * (R_j*vp + t_j)
// ---------------------------------------------------------------------------
__global__ void __launch_bounds__(256) k4_skin(const float* __restrict__ weights,
                                               const float* __restrict__ trans,
                                               float* __restrict__ out) {
    int tid = threadIdx.x;        // 256 = 8 warps
    int warp = tid >> 5;
    int lane = tid & 31;
    int b = blockIdx.y * 8 + warp;

    __shared__ float4 s_rel[8][J*3];
    {
        const float4* src = reinterpret_cast<const float4*>(g_rel);
        for (int i = tid; i < 8*J*3; i += 256) {
            int bl = i / (J*3), e = i % (J*3);
            s_rel[bl][e] = src[(size_t)(blockIdx.y*8 + bl)*(J*3) + e];
        }
    }
    __syncthreads();

    float t0 = trans[b*3+0], t1 = trans[b*3+1], t2 = trans[b*3+2];
    const float4* rel = s_rel[warp];
    const size_t bbase = (size_t)b * VS;

    int v0 = blockIdx.x * 128;
    int v[4]; bool ok[4];
    float vx[4], vy[4], vz[4];
    #pragma unroll
    for (int u = 0; u < 4; u++) {
        int vv = v0 + u*32 + lane;
        ok[u] = vv < V;
        v[u] = ok[u] ? vv : (V - 1);
        vx[u] = g_vposed[bbase + v[u]*3 + 0];
        vy[u] = g_vposed[bbase + v[u]*3 + 1];
        vz[u] = g_vposed[bbase + v[u]*3 + 2];
    }

    u64 vx2[2], vy2[2], vz2[2], ox2[2], oy2[2], oz2[2];
    #pragma unroll
    for (int p = 0; p < 2; p++) {
        vx2[p] = pk2(vx[2*p], vx[2*p+1]);
        vy2[p] = pk2(vy[2*p], vy[2*p+1]);
        vz2[p] = pk2(vz[2*p], vz[2*p+1]);
        ox2[p] = pk2(t0, t0);
        oy2[p] = pk2(t1, t1);
        oz2[p] = pk2(t2, t2);
    }

    const float4* wv0 = reinterpret_cast<const float4*>(weights + (size_t)v[0]*J);
    const float4* wv1 = reinterpret_cast<const float4*>(weights + (size_t)v[1]*J);
    const float4* wv2 = reinterpret_cast<const float4*>(weights + (size_t)v[2]*J);
    const float4* wv3 = reinterpret_cast<const float4*>(weights + (size_t)v[3]*J);

    #pragma unroll
    for (int q = 0; q < 6; q++) {
        float4 w[4];
        w[0] = wv0[q]; w[1] = wv1[q]; w[2] = wv2[q]; w[3] = wv3[q];
        #pragma unroll
        for (int jj = 0; jj < 4; jj++) {
            int j = q*4 + jj;
            float4 r0 = rel[j*3 + 0];
            float4 r1 = rel[j*3 + 1];
            float4 r2 = rel[j*3 + 2];
            u64 r0x = pk2(r0.x, r0.x), r0y = pk2(r0.y, r0.y), r0z = pk2(r0.z, r0.z), r0w = pk2(r0.w, r0.w);
            u64 r1x = pk2(r1.x, r1.x), r1y = pk2(r1.y, r1.y), r1z = pk2(r1.z, r1.z), r1w = pk2(r1.w, r1.w);
            u64 r2x = pk2(r2.x, r2.x), r2y = pk2(r2.y, r2.y), r2z = pk2(r2.z, r2.z), r2w = pk2(r2.w, r2.w);
            float wj[4];
            #pragma unroll
            for (int u = 0; u < 4; u++)
                wj[u] = (jj == 0) ? w[u].x : (jj == 1) ? w[u].y : (jj == 2) ? w[u].z : w[u].w;
            #pragma unroll
            for (int p = 0; p < 2; p++) {
                u64 w2 = pk2(wj[2*p], wj[2*p+1]);
                u64 rx = fma2(r0x, vx2[p], fma2(r0y, vy2[p], fma2(r0z, vz2[p], r0w)));
                u64 ry = fma2(r1x, vx2[p], fma2(r1y, vy2[p], fma2(r1z, vz2[p], r1w)));
                u64 rz = fma2(r2x, vx2[p], fma2(r2y, vy2[p], fma2(r2z, vz2[p], r2w)));
                ox2[p] = fma2(w2, rx, ox2[p]);
                oy2[p] = fma2(w2, ry, oy2[p]);
                oz2[p] = fma2(w2, rz, oz2[p]);
            }
        }
    }

    #pragma unroll
    for (int p = 0; p < 2; p++) {
        float oxl, oxh, oyl, oyh, ozl, ozh;
        upk(ox2[p], oxl, oxh);
        upk(oy2[p], oyl, oyh);
        upk(oz2[p], ozl, ozh);
        if (ok[2*p]) {
            float* o = out + ((size_t)b*V + v[2*p])*3;
            o[0] = oxl; o[1] = oyl; o[2] = ozl;
        }
        if (ok[2*p+1]) {
            float* o = out + ((size_t)b*V + v[2*p+1])*3;
            o[0] = oxh; o[1] = oyh; o[2] = ozh;
        }
    }
}

// ---------------------------------------------------------------------------
extern "C" void kernel_launch(void* const* d_in, const int* in_sizes, int n_in,
                              void* d_out, int out_size) {
    const float* root_orient = (const float*)d_in[0];
    const float* pose_body   = (const float*)d_in[1];
    const float* pose_hand   = (const float*)d_in[2];
    const float* betas       = (const float*)d_in[3];
    const float* trans       = (const float*)d_in[4];
    const float* v_template  = (const float*)d_in[5];
    const float* shapedirs   = (const float*)d_in[6];
    const float* posedirs    = (const float*)d_in[7];
    const float* J_regressor = (const float*)d_in[8];
    const float* weights     = (const float*)d_in[9];

    float* out = (float*)d_out;
    float* out_joints = out + (size_t)B * V * 3;

    k0_pack<<<dim3(81, KT), 256>>>(posedirs, shapedirs);
    k1_regress<<<dim3(J, 33), 256>>>(J_regressor, v_template, shapedirs);
    k2_pose<<<B, 32>>>(root_orient, pose_body, pose_hand, betas, trans, out_joints);
    k3_tf32<<<dim3(VS/128, B/128), 256>>>(v_template);
    k4_skin<<<dim3((V + 127)/128, B/8), 256>>>(weights, trans, out);
}